// round 8
// baseline (speedup 1.0000x reference)
#include <cuda_runtime.h>
#include <cuda_bf16.h>
#include <float.h>

#define N_NODES 100000
#define N_EDGES 1600000
#define FDIM    32
#define NEG_SLOPE 0.2f

// ---------------- scratch (static device globals; no allocation) ------------
__device__ __align__(16) float g_xl [N_NODES * FDIM];   // source transform
__device__ __align__(16) float g_xr [N_NODES * FDIM];   // target transform
__device__ __align__(16) float g_h  [N_NODES * FDIM];   // layer-1 output (relu'd)
__device__ int   g_icnt  [N_NODES];       // in-degree (int)
__device__ float g_suma  [N_NODES];       // sum of edge_attr per target
__device__ float g_mean  [N_NODES];       // self-loop attr (mean fill)
__device__ int   g_rowptr[N_NODES + 1];   // CSR row pointers (by dst)
__device__ int   g_cursor[N_NODES];       // fill cursors
__device__ int   g_csrs  [N_EDGES];       // CSR src ids
__device__ float g_csra  [N_EDGES];       // CSR edge attrs

// ---------------- build kernels ---------------------------------------------

__global__ void k_init() {
    int i = blockIdx.x * blockDim.x + threadIdx.x;
    if (i < N_NODES) { g_icnt[i] = 0; g_suma[i] = 0.0f; }
}

__global__ void k_stats(const int* __restrict__ dst, const float* __restrict__ ea) {
    int e = blockIdx.x * blockDim.x + threadIdx.x;
    if (e < N_EDGES) {
        int d = dst[e];
        atomicAdd(&g_icnt[d], 1);
        atomicAdd(&g_suma[d], ea[e]);
    }
}

// single-block exclusive scan of g_icnt -> g_rowptr / g_cursor
__global__ void __launch_bounds__(1024) k_scan() {
    __shared__ int sdata[1024];
    int tid = threadIdx.x;
    const int CH = (N_NODES + 1023) / 1024;          // 98
    int beg = tid * CH;
    int end = min(beg + CH, N_NODES);
    int sum = 0;
    for (int i = beg; i < end; i++) sum += g_icnt[i];
    sdata[tid] = sum;
    __syncthreads();
    for (int off = 1; off < 1024; off <<= 1) {       // Hillis-Steele inclusive
        int v = (tid >= off) ? sdata[tid - off] : 0;
        __syncthreads();
        sdata[tid] += v;
        __syncthreads();
    }
    int prefix = (tid == 0) ? 0 : sdata[tid - 1];
    for (int i = beg; i < end; i++) {
        g_rowptr[i] = prefix;
        g_cursor[i] = prefix;
        prefix += g_icnt[i];
    }
    if (tid == 1023) g_rowptr[N_NODES] = prefix;     // = N_EDGES
}

__global__ void k_mean() {
    int i = blockIdx.x * blockDim.x + threadIdx.x;
    if (i < N_NODES) g_mean[i] = g_suma[i] / fmaxf((float)g_icnt[i], 1.0f);
}

__global__ void k_fill(const int* __restrict__ src, const int* __restrict__ dst,
                       const float* __restrict__ ea) {
    int e = blockIdx.x * blockDim.x + threadIdx.x;
    if (e < N_EDGES) {
        int d   = dst[e];
        int pos = atomicAdd(&g_cursor[d], 1);
        g_csrs[pos] = src[e];
        g_csra[pos] = ea[e];
    }
}

// ---------------- GEMM -------------------------------------------------------
// X[rows,K] @ Wl/Wr[K,32] + bias -> g_xl/g_xr.
// 64 rows/block, 256 threads; warp w = rows base+8w..+7, lane = out col.
// x staged in SMEM (coalesced fill), inner reads are warp-uniform broadcast
// LDS.128. W (16KB each, L1-resident) read via coalesced __ldg.
template <int K>
__global__ void __launch_bounds__(256) k_gemm(
        const float4* __restrict__ Xin,
        const float* __restrict__ Wl, const float* __restrict__ bl,
        const float* __restrict__ Wr, const float* __restrict__ br) {
    __shared__ float4 sx[64 * (K / 4)];              // 32KB (K=128) / 8KB (K=32)
    const float4* X4 = Xin ? Xin : (const float4*)g_h;

    int tid  = threadIdx.x;
    int base = blockIdx.x * 64;
    for (int i = tid; i < 64 * (K / 4); i += 256) {
        int row = base + i / (K / 4);
        int kk  = i % (K / 4);
        if (row >= N_NODES) row = N_NODES - 1;       // clamp (stores guarded)
        sx[i] = X4[(long)row * (K / 4) + kk];
    }
    __syncthreads();

    int col = tid & 31;
    int ty  = tid >> 5;

    float al[8], ar[8];
    #pragma unroll
    for (int r = 0; r < 8; r++) { al[r] = 0.f; ar[r] = 0.f; }

    #pragma unroll 4
    for (int k4 = 0; k4 < K / 4; k4++) {
        float wl0 = __ldg(&Wl[(k4 * 4 + 0) * 32 + col]);
        float wl1 = __ldg(&Wl[(k4 * 4 + 1) * 32 + col]);
        float wl2 = __ldg(&Wl[(k4 * 4 + 2) * 32 + col]);
        float wl3 = __ldg(&Wl[(k4 * 4 + 3) * 32 + col]);
        float wr0 = __ldg(&Wr[(k4 * 4 + 0) * 32 + col]);
        float wr1 = __ldg(&Wr[(k4 * 4 + 1) * 32 + col]);
        float wr2 = __ldg(&Wr[(k4 * 4 + 2) * 32 + col]);
        float wr3 = __ldg(&Wr[(k4 * 4 + 3) * 32 + col]);
        #pragma unroll
        for (int r = 0; r < 8; r++) {
            float4 xv = sx[(ty * 8 + r) * (K / 4) + k4];   // warp-uniform bcast
            al[r] = fmaf(xv.x, wl0, al[r]);
            al[r] = fmaf(xv.y, wl1, al[r]);
            al[r] = fmaf(xv.z, wl2, al[r]);
            al[r] = fmaf(xv.w, wl3, al[r]);
            ar[r] = fmaf(xv.x, wr0, ar[r]);
            ar[r] = fmaf(xv.y, wr1, ar[r]);
            ar[r] = fmaf(xv.z, wr2, ar[r]);
            ar[r] = fmaf(xv.w, wr3, ar[r]);
        }
    }
    float bL = bl[col], bR = br[col];
    int row0 = base + ty * 8;
    #pragma unroll
    for (int r = 0; r < 8; r++) {
        int row = row0 + r;
        if (row < N_NODES) {
            g_xl[row * 32 + col] = al[r] + bL;
            g_xr[row * 32 + col] = ar[r] + bR;
        }
    }
}

// ---------------- node-parallel fused attention + aggregation ---------------
// Warp per node n (lane = feature). Reads xr[n] once, loops over incoming CSR
// edges (+implicit self-loop) with 2-deep src prefetch, accumulates Σp·xl and
// Σp in registers, writes normalized+biased output directly (relu for layer 1).
__global__ void __launch_bounds__(256) k_node(
        const float* __restrict__ We, const float* __restrict__ att,
        const float* __restrict__ b, float* __restrict__ out, int do_relu) {
    int warp = (blockIdx.x * blockDim.x + threadIdx.x) >> 5;
    int lane = threadIdx.x & 31;
    if (warp >= N_NODES) return;
    const int n = warp;

    float xr = g_xl == nullptr ? 0.f : g_xr[n * 32 + lane];
    float w  = __ldg(&We[lane]);
    float at = __ldg(&att[lane]);

    float acc, z;
    {   // self loop: s = n, attr = mean[n]
        float xl = g_xl[n * 32 + lane];
        float v  = xl + xr + g_mean[n] * w;
        v = v > 0.f ? v : NEG_SLOPE * v;
        float t = v * at;
        t += __shfl_xor_sync(0xffffffffu, t, 16);
        t += __shfl_xor_sync(0xffffffffu, t, 8);
        t += __shfl_xor_sync(0xffffffffu, t, 4);
        t += __shfl_xor_sync(0xffffffffu, t, 2);
        t += __shfl_xor_sync(0xffffffffu, t, 1);
        float p = __expf(t);
        acc = p * xl;
        z   = p;
    }

    int beg = g_rowptr[n];
    int end = g_rowptr[n + 1];
    int   s_nx = 0; float a_nx = 0.f;
    if (beg < end) { s_nx = g_csrs[beg]; a_nx = g_csra[beg]; }
    for (int j = beg; j < end; j++) {
        int   s = s_nx;
        float a = a_nx;
        if (j + 1 < end) { s_nx = g_csrs[j + 1]; a_nx = g_csra[j + 1]; }
        float xl = g_xl[s * 32 + lane];
        float v  = xl + xr + a * w;
        v = v > 0.f ? v : NEG_SLOPE * v;
        float t = v * at;
        t += __shfl_xor_sync(0xffffffffu, t, 16);
        t += __shfl_xor_sync(0xffffffffu, t, 8);
        t += __shfl_xor_sync(0xffffffffu, t, 4);
        t += __shfl_xor_sync(0xffffffffu, t, 2);
        t += __shfl_xor_sync(0xffffffffu, t, 1);
        float p = __expf(t);
        acc = fmaf(p, xl, acc);
        z  += p;
    }

    float o = acc / z + __ldg(&b[lane]);
    if (do_relu) { g_h[n * 32 + lane] = fmaxf(o, 0.f); }
    else         { out[n * 32 + lane] = o; }
}

// ---------------- launch ----------------------------------------------------
extern "C" void kernel_launch(void* const* d_in, const int* in_sizes, int n_in,
                              void* d_out, int out_size) {
    const float* x    = (const float*)d_in[0];
    const int*   src  = (const int*)  d_in[1];
    const int*   dst  = (const int*)  d_in[2];
    const float* ea   = (const float*)d_in[3];
    const float* Wl1  = (const float*)d_in[4];
    const float* bl1  = (const float*)d_in[5];
    const float* Wr1  = (const float*)d_in[6];
    const float* br1  = (const float*)d_in[7];
    const float* We1  = (const float*)d_in[8];
    const float* att1 = (const float*)d_in[9];
    const float* b1   = (const float*)d_in[10];
    const float* Wl2  = (const float*)d_in[11];
    const float* bl2  = (const float*)d_in[12];
    const float* Wr2  = (const float*)d_in[13];
    const float* br2  = (const float*)d_in[14];
    const float* We2  = (const float*)d_in[15];
    const float* att2 = (const float*)d_in[16];
    const float* b2   = (const float*)d_in[17];
    float* out = (float*)d_out;

    const int TB = 256;
    const int NB = (N_NODES + TB - 1) / TB;
    const int EB = (N_EDGES + TB - 1) / TB;
    const int WB = (N_NODES * 32 + TB - 1) / TB;     // warp per node
    const int GB = (N_NODES + 63) / 64;

    // CSR build (layer-invariant) + self-loop mean attrs
    k_init<<<NB, TB>>>();
    k_stats<<<EB, TB>>>(dst, ea);
    k_scan<<<1, 1024>>>();
    k_mean<<<NB, TB>>>();
    k_fill<<<EB, TB>>>(src, dst, ea);

    // ---- layer 1 ----
    k_gemm<128><<<GB, TB>>>((const float4*)x, Wl1, bl1, Wr1, br1);
    k_node<<<WB, TB>>>(We1, att1, b1, out, 1);

    // ---- layer 2 ----
    k_gemm<32><<<GB, TB>>>(nullptr, Wl2, bl2, Wr2, br2);
    k_node<<<WB, TB>>>(We2, att2, b2, out, 0);
}

// round 9
// speedup vs baseline: 1.7644x; 1.7644x over previous
#include <cuda_runtime.h>
#include <cuda_bf16.h>
#include <float.h>

#define N_NODES 100000
#define N_EDGES 1600000
#define FDIM    32
#define NEG_SLOPE 0.2f

// ---------------- scratch (static device globals; no allocation) ------------
__device__ __align__(16) float g_xl [N_NODES * FDIM];   // source transform
__device__ __align__(16) float g_xr [N_NODES * FDIM];   // target transform
__device__ __align__(16) float g_h  [N_NODES * FDIM];   // layer-1 output (relu'd)
__device__ __align__(16) float g_acc[N_NODES * FDIM];   // unnormalized aggregation
                                                        // invariant: zero between launches
__device__ float g_z1  [N_NODES];         // sum of exp(score), layer 1
__device__ float g_z2  [N_NODES];         // sum of exp(score), layer 2
__device__ float g_cnt [N_NODES];         // in-degree (float, matches ref)
__device__ float g_suma[N_NODES];         // sum of edge_attr per target

// ---------------- kernels ---------------------------------------------------

// per-launch reset of the small node state only. g_acc stays zero by the
// k_fin invariant (read+reset by the same thread), so no 12.8MB pass here.
__global__ void k_init() {
    int i = blockIdx.x * blockDim.x + threadIdx.x;
    if (i < N_NODES) { g_z1[i] = 0.0f; g_z2[i] = 0.0f; g_cnt[i] = 0.0f; g_suma[i] = 0.0f; }
}

__global__ void k_stats(const int* __restrict__ dst, const float* __restrict__ ea) {
    int e = blockIdx.x * blockDim.x + threadIdx.x;
    if (e < N_EDGES) {
        int d = dst[e];
        atomicAdd(&g_cnt[d], 1.0f);
        atomicAdd(&g_suma[d], ea[e]);
    }
}

// X[rows,K] @ Wl/Wr[K,32] + bias -> g_xl/g_xr.
// 64 rows/block, 256 threads; warp w = rows base+8w..+7, lane = out col.
// x staged in SMEM (coalesced fill), inner reads are warp-uniform broadcast
// LDS.128. W (16KB each, L1-resident) read via coalesced __ldg.
template <int K>
__global__ void __launch_bounds__(256) k_gemm(
        const float4* __restrict__ Xin,
        const float* __restrict__ Wl, const float* __restrict__ bl,
        const float* __restrict__ Wr, const float* __restrict__ br) {
    __shared__ float4 sx[64 * (K / 4)];              // 32KB (K=128) / 8KB (K=32)
    const float4* X4 = Xin ? Xin : (const float4*)g_h;

    int tid  = threadIdx.x;
    int base = blockIdx.x * 64;
    for (int i = tid; i < 64 * (K / 4); i += 256) {
        int row = base + i / (K / 4);
        int kk  = i % (K / 4);
        if (row >= N_NODES) row = N_NODES - 1;       // clamp (stores guarded)
        sx[i] = X4[(long)row * (K / 4) + kk];
    }
    __syncthreads();

    int col = tid & 31;
    int ty  = tid >> 5;

    float al[8], ar[8];
    #pragma unroll
    for (int r = 0; r < 8; r++) { al[r] = 0.f; ar[r] = 0.f; }

    #pragma unroll 4
    for (int k4 = 0; k4 < K / 4; k4++) {
        float wl0 = __ldg(&Wl[(k4 * 4 + 0) * 32 + col]);
        float wl1 = __ldg(&Wl[(k4 * 4 + 1) * 32 + col]);
        float wl2 = __ldg(&Wl[(k4 * 4 + 2) * 32 + col]);
        float wl3 = __ldg(&Wl[(k4 * 4 + 3) * 32 + col]);
        float wr0 = __ldg(&Wr[(k4 * 4 + 0) * 32 + col]);
        float wr1 = __ldg(&Wr[(k4 * 4 + 1) * 32 + col]);
        float wr2 = __ldg(&Wr[(k4 * 4 + 2) * 32 + col]);
        float wr3 = __ldg(&Wr[(k4 * 4 + 3) * 32 + col]);
        #pragma unroll
        for (int r = 0; r < 8; r++) {
            float4 xv = sx[(ty * 8 + r) * (K / 4) + k4];   // warp-uniform bcast
            al[r] = fmaf(xv.x, wl0, al[r]);
            al[r] = fmaf(xv.y, wl1, al[r]);
            al[r] = fmaf(xv.z, wl2, al[r]);
            al[r] = fmaf(xv.w, wl3, al[r]);
            ar[r] = fmaf(xv.x, wr0, ar[r]);
            ar[r] = fmaf(xv.y, wr1, ar[r]);
            ar[r] = fmaf(xv.z, wr2, ar[r]);
            ar[r] = fmaf(xv.w, wr3, ar[r]);
        }
    }
    float bL = bl[col], bR = br[col];
    int row0 = base + ty * 8;
    #pragma unroll
    for (int r = 0; r < 8; r++) {
        int row = row0 + r;
        if (row < N_NODES) {
            g_xl[row * 32 + col] = al[r] + bL;
            g_xr[row * 32 + col] = ar[r] + bR;
        }
    }
}

// Fused edge pass over the REAL edges only (self-loops handled in k_fin):
// 8 lanes per edge, each lane owns a float4 feature group.
// p = exp(score) (shift-invariant softmax) -> acc[d] += p*xl[s], z[d] += p.
__global__ void k_edge(const int* __restrict__ src, const int* __restrict__ dst,
                       const float* __restrict__ ea,
                       const float* __restrict__ We, const float* __restrict__ att,
                       int zsel) {
    int g   = blockIdx.x * blockDim.x + threadIdx.x;
    int e   = g >> 3;
    int sub = g & 7;
    if (e >= N_EDGES) return;

    int s = src[e], d = dst[e];
    float a = ea[e];

    // issue long-latency gathers first
    float4 xl4 = __ldg(&((const float4*)g_xl)[s * 8 + sub]);
    float4 xr4 = __ldg(&((const float4*)g_xr)[d * 8 + sub]);
    float4 W4  = __ldg(&((const float4*)We)[sub]);
    float4 A4  = __ldg(&((const float4*)att)[sub]);

    float v0 = xl4.x + xr4.x + a * W4.x;
    float v1 = xl4.y + xr4.y + a * W4.y;
    float v2 = xl4.z + xr4.z + a * W4.z;
    float v3 = xl4.w + xr4.w + a * W4.w;
    v0 = v0 > 0.f ? v0 : NEG_SLOPE * v0;
    v1 = v1 > 0.f ? v1 : NEG_SLOPE * v1;
    v2 = v2 > 0.f ? v2 : NEG_SLOPE * v2;
    v3 = v3 > 0.f ? v3 : NEG_SLOPE * v3;

    float t = v0 * A4.x + v1 * A4.y + v2 * A4.z + v3 * A4.w;
    t += __shfl_xor_sync(0xffffffffu, t, 1);
    t += __shfl_xor_sync(0xffffffffu, t, 2);
    t += __shfl_xor_sync(0xffffffffu, t, 4);

    float p = __expf(t);

    float c0 = p * xl4.x, c1 = p * xl4.y, c2 = p * xl4.z, c3 = p * xl4.w;
    float* dstp = &g_acc[d * 32 + sub * 4];
    asm volatile("red.global.add.v4.f32 [%0], {%1, %2, %3, %4};"
                 :: "l"(dstp), "f"(c0), "f"(c1), "f"(c2), "f"(c3) : "memory");
    if (sub == 0) atomicAdd(zsel ? &g_z2[d] : &g_z1[d], p);
}

// finalize: add the self-loop contribution (attr = suma/max(cnt,1)), divide,
// add bias; layer1 -> relu into g_h, layer2 -> d_out. Warps are node-aligned
// (block=256): node n = i>>5, lane = feature. Resets g_acc (same-thread).
__global__ void __launch_bounds__(256) k_fin(
        const float* __restrict__ We, const float* __restrict__ att,
        const float* __restrict__ b, float* __restrict__ out,
        int zsel, int do_relu) {
    int i = blockIdx.x * blockDim.x + threadIdx.x;
    if (i >= N_NODES * FDIM) return;
    int n    = i >> 5;
    int lane = i & 31;

    float xl  = g_xl[i];
    float xr  = g_xr[i];
    float acc = g_acc[i];
    float z   = zsel ? g_z2[n] : g_z1[n];
    float mean = g_suma[n] / fmaxf(g_cnt[n], 1.0f);

    float v = xl + xr + mean * __ldg(&We[lane]);
    v = v > 0.f ? v : NEG_SLOPE * v;
    float t = v * __ldg(&att[lane]);
    t += __shfl_xor_sync(0xffffffffu, t, 1);
    t += __shfl_xor_sync(0xffffffffu, t, 2);
    t += __shfl_xor_sync(0xffffffffu, t, 4);
    t += __shfl_xor_sync(0xffffffffu, t, 8);
    t += __shfl_xor_sync(0xffffffffu, t, 16);
    float p = __expf(t);

    float o = (acc + p * xl) / (z + p) + __ldg(&b[lane]);
    if (do_relu) g_h[i] = fmaxf(o, 0.f);
    else         out[i] = o;
    g_acc[i] = 0.0f;                      // restore zero invariant
}

// ---------------- launch ----------------------------------------------------
extern "C" void kernel_launch(void* const* d_in, const int* in_sizes, int n_in,
                              void* d_out, int out_size) {
    const float* x    = (const float*)d_in[0];
    const int*   src  = (const int*)  d_in[1];
    const int*   dst  = (const int*)  d_in[2];
    const float* ea   = (const float*)d_in[3];
    const float* Wl1  = (const float*)d_in[4];
    const float* bl1  = (const float*)d_in[5];
    const float* Wr1  = (const float*)d_in[6];
    const float* br1  = (const float*)d_in[7];
    const float* We1  = (const float*)d_in[8];
    const float* att1 = (const float*)d_in[9];
    const float* b1   = (const float*)d_in[10];
    const float* Wl2  = (const float*)d_in[11];
    const float* bl2  = (const float*)d_in[12];
    const float* Wr2  = (const float*)d_in[13];
    const float* br2  = (const float*)d_in[14];
    const float* We2  = (const float*)d_in[15];
    const float* att2 = (const float*)d_in[16];
    const float* b2   = (const float*)d_in[17];
    float* out = (float*)d_out;

    const int TB   = 256;
    const int NB   = (N_NODES + TB - 1) / TB;
    const int NB32 = (N_NODES * FDIM + TB - 1) / TB;
    const int EB   = (N_EDGES + TB - 1) / TB;
    const int XB   = ((long)N_EDGES * 8 + TB - 1) / TB;   // oct per edge
    const int GB   = (N_NODES + 63) / 64;

    // per-launch node-state reset + degree stats (self-loop attrs)
    k_init<<<NB, TB>>>();
    k_stats<<<EB, TB>>>(dst, ea);

    // ---- layer 1 ----
    k_gemm<128><<<GB, TB>>>((const float4*)x, Wl1, bl1, Wr1, br1);
    k_edge<<<XB, TB>>>(src, dst, ea, We1, att1, 0);
    k_fin<<<NB32, TB>>>(We1, att1, b1, out, 0, 1);

    // ---- layer 2 ----
    k_gemm<32><<<GB, TB>>>(nullptr, Wl2, bl2, Wr2, br2);
    k_edge<<<XB, TB>>>(src, dst, ea, We2, att2, 1);
    k_fin<<<NB32, TB>>>(We2, att2, b2, out, 1, 0);
}